// round 1
// baseline (speedup 1.0000x reference)
#include <cuda_runtime.h>
#include <math.h>
#include <stdint.h>

#define NN 50000
#define NE 600000
#define DD 128
#define EPS_V 1e-5f
// AVG_D_LOG = log(5)
#define AVG_D_LOG 1.6094379124341003f

// ---------------- scratch (static device globals; no runtime alloc) ----------------
__device__ float g_PQ[(size_t)NN * 256];       // [P | Q+b_pre]
__device__ float g_agg[(size_t)NN * 512];      // [mean | max | min | std]
__device__ float g_G[(size_t)NN * 384];        // agg @ Wcat
__device__ float g_hp[(size_t)NN * 128];
__device__ float g_s1[NN];
__device__ float g_s2[NN];
__device__ int   g_count[NN];
__device__ int   g_offsets[NN + 1];
__device__ int   g_cursor[NN];
__device__ int   g_sorted_src[NE];
__device__ float g_B1[128 * 256];
__device__ float g_Wcat[512 * 384];
__device__ float g_bias1[256];
__device__ int   g_is64;

// ---------------- index dtype detection ----------------
__global__ void detect_kernel(const void* edst) {
    const int* v = (const int*)edst;
    // int64 little-endian: words 1,3 are high halves of values < 50000 -> 0.
    // int32: v[1]=1, v[3]=3 (arange prefix).
    g_is64 = (v[1] == 0 && v[3] == 0) ? 1 : 0;
}

__device__ __forceinline__ int edge_index(const void* p, int i) {
    if (g_is64) return (int)(((const long long*)p)[i]);
    return ((const int*)p)[i];
}

// ---------------- prep: zero counters, pack B1 / Wcat / bias1 ----------------
__global__ void prep_kernel(const float* __restrict__ W_pre,
                            const float* __restrict__ b_pre,
                            const float* __restrict__ W_post) {
    int idx = blockIdx.x * blockDim.x + threadIdx.x;
    if (idx < NN) g_count[idx] = 0;
    if (idx < 256) g_bias1[idx] = (idx < 128) ? 0.f : b_pre[idx - 128];
    if (idx < 128 * 256) {
        int k = idx >> 8;
        int c = idx & 255;
        g_B1[idx] = (c < 128) ? W_pre[k * 128 + c] : W_pre[(128 + k) * 128 + (c - 128)];
    }
    if (idx < 512 * 384) {
        int k = idx / 384;
        int j = idx % 384;
        int grp = j >> 7;          // 0: identity, 1: amplification, 2: attenuation
        int jj = j & 127;
        g_Wcat[idx] = W_post[(size_t)(128 + grp * 512 + k) * 128 + jj];
    }
}

// ---------------- histogram of edge_dst ----------------
__global__ void hist_kernel(const void* __restrict__ edst) {
    int e = blockIdx.x * blockDim.x + threadIdx.x;
    if (e < NE) {
        int d = edge_index(edst, e);
        atomicAdd(&g_count[d], 1);
    }
}

// ---------------- single-block exclusive scan -> offsets, cursor ----------------
__global__ void scan_kernel() {
    __shared__ int sdata[1024];
    __shared__ int s_total;
    int tid = threadIdx.x;
    if (tid == 0) s_total = 0;
    __syncthreads();
    for (int base = 0; base < NN; base += 1024) {
        int tot = s_total;
        int i = base + tid;
        int v = (i < NN) ? g_count[i] : 0;
        sdata[tid] = v;
        __syncthreads();
        // Hillis-Steele inclusive scan
        #pragma unroll
        for (int off = 1; off < 1024; off <<= 1) {
            int t = (tid >= off) ? sdata[tid - off] : 0;
            __syncthreads();
            sdata[tid] += t;
            __syncthreads();
        }
        int incl = sdata[tid];
        if (i < NN) {
            int excl = tot + incl - v;
            g_offsets[i] = excl;
            g_cursor[i] = excl;
        }
        __syncthreads();
        if (tid == 0) s_total = tot + sdata[1023];
        __syncthreads();
    }
    if (tid == 0) g_offsets[NN] = NE;
}

// ---------------- scatter edges into CSR order ----------------
__global__ void scatter_kernel(const void* __restrict__ esrc, const void* __restrict__ edst) {
    int e = blockIdx.x * blockDim.x + threadIdx.x;
    if (e < NE) {
        int d = edge_index(edst, e);
        int s = edge_index(esrc, e);
        int pos = atomicAdd(&g_cursor[d], 1);
        g_sorted_src[pos] = s;
    }
}

// ---------------- generic 128x128-tile SGEMM with epilogue modes ----------------
// mode 0: C = acc (+bias)                                  [GEMM1, GEMM2]
// mode 1: C = relu(acc + bias + G0 + s1*G1 + s2*G2)        [hp; N must be 128]
// mode 2: C = resid + leaky_relu(acc + bias)               [out; N must be 128]
__global__ void __launch_bounds__(256) sgemm_kernel(
    const float* __restrict__ A, const float* __restrict__ B, float* __restrict__ C,
    int M, int N, int K, int mode,
    const float* __restrict__ bias,
    const float* __restrict__ Gx,
    const float* __restrict__ s1p, const float* __restrict__ s2p,
    const float* __restrict__ resid)
{
    __shared__ float As[16][128];
    __shared__ float Bs[16][128];
    int tid = threadIdx.x;
    int blockRow = blockIdx.x * 128;
    int blockCol = blockIdx.y * 128;
    int tr = (tid / 16) * 8;
    int tc = (tid % 16) * 8;

    float acc[8][8];
    #pragma unroll
    for (int i = 0; i < 8; i++)
        #pragma unroll
        for (int j = 0; j < 8; j++) acc[i][j] = 0.f;

    int aRow0 = tid >> 2;         // 0..63
    int aCol  = (tid & 3) * 4;    // 0,4,8,12
    int bRow0 = tid >> 5;         // 0..7
    int bCol  = (tid & 31) * 4;   // 0..124

    for (int k0 = 0; k0 < K; k0 += 16) {
        #pragma unroll
        for (int half = 0; half < 2; half++) {
            int r = aRow0 + half * 64;
            int gr = blockRow + r;
            if (gr > M - 1) gr = M - 1;
            float4 v = *reinterpret_cast<const float4*>(&A[(size_t)gr * K + k0 + aCol]);
            As[aCol + 0][r] = v.x;
            As[aCol + 1][r] = v.y;
            As[aCol + 2][r] = v.z;
            As[aCol + 3][r] = v.w;
        }
        #pragma unroll
        for (int half = 0; half < 2; half++) {
            int r = bRow0 + half * 8;
            float4 v = *reinterpret_cast<const float4*>(&B[(size_t)(k0 + r) * N + blockCol + bCol]);
            *reinterpret_cast<float4*>(&Bs[r][bCol]) = v;
        }
        __syncthreads();
        #pragma unroll
        for (int k = 0; k < 16; k++) {
            float4 a0 = *reinterpret_cast<float4*>(&As[k][tr]);
            float4 a1 = *reinterpret_cast<float4*>(&As[k][tr + 4]);
            float4 b0 = *reinterpret_cast<float4*>(&Bs[k][tc]);
            float4 b1 = *reinterpret_cast<float4*>(&Bs[k][tc + 4]);
            float ra[8] = {a0.x, a0.y, a0.z, a0.w, a1.x, a1.y, a1.z, a1.w};
            float rb[8] = {b0.x, b0.y, b0.z, b0.w, b1.x, b1.y, b1.z, b1.w};
            #pragma unroll
            for (int i = 0; i < 8; i++)
                #pragma unroll
                for (int j = 0; j < 8; j++)
                    acc[i][j] = fmaf(ra[i], rb[j], acc[i][j]);
        }
        __syncthreads();
    }

    #pragma unroll
    for (int i = 0; i < 8; i++) {
        int row = blockRow + tr + i;
        if (row >= M) break;
        float s1v = 0.f, s2v = 0.f;
        if (mode == 1) { s1v = s1p[row]; s2v = s2p[row]; }
        #pragma unroll
        for (int j = 0; j < 8; j++) {
            int col = blockCol + tc + j;
            float v = acc[i][j];
            if (bias) v += bias[col];
            if (mode == 1) {
                const float* g = &Gx[(size_t)row * 384];
                v += g[col] + s1v * g[col + 128] + s2v * g[col + 256];
                v = fmaxf(v, 0.f);
            } else if (mode == 2) {
                v = (v > 0.f) ? v : 0.01f * v;
                v += resid[(size_t)row * 128 + col];
            }
            C[(size_t)row * N + col] = v;
        }
    }
}

// ---------------- per-node multi-aggregator ----------------
__global__ void __launch_bounds__(128) aggregate_kernel() {
    int n = blockIdx.x;
    int d = threadIdx.x;
    int start = g_offsets[n];
    int end = g_offsets[n + 1];
    float qd = g_PQ[(size_t)n * 256 + 128 + d];
    float s = 0.f, sq = 0.f;
    float mx = -3.4e38f, mn = 3.4e38f;
    for (int i = start; i < end; i++) {
        int src = g_sorted_src[i];
        float v = g_PQ[(size_t)src * 256 + d] + qd;
        v = fmaxf(v, 0.f);
        s += v;
        sq += v * v;
        mx = fmaxf(mx, v);
        mn = fminf(mn, v);
    }
    float degf = (float)(end - start);   // >= 1 (guaranteed self loop)
    float inv = 1.f / degf;
    float mean = s * inv;
    float msq = sq * inv;
    float var = fmaxf(msq - mean * mean, 0.f);
    float sd = sqrtf(var + EPS_V);
    size_t base = (size_t)n * 512;
    g_agg[base + d] = mean;
    g_agg[base + 128 + d] = mx;
    g_agg[base + 256 + d] = mn;
    g_agg[base + 384 + d] = sd;
    if (d == 0) {
        float ld = logf(degf + 1.f);
        g_s1[n] = ld / AVG_D_LOG;
        g_s2[n] = AVG_D_LOG / ld;
    }
}

// ---------------- launch ----------------
extern "C" void kernel_launch(void* const* d_in, const int* in_sizes, int n_in,
                              void* d_out, int out_size) {
    const float* h      = (const float*)d_in[0];
    const void*  esrc   = d_in[1];
    const void*  edst   = d_in[2];
    const float* W_pre  = (const float*)d_in[3];
    const float* b_pre  = (const float*)d_in[4];
    const float* W_post = (const float*)d_in[5];
    const float* b_post = (const float*)d_in[6];
    const float* W_mix  = (const float*)d_in[7];
    const float* b_mix  = (const float*)d_in[8];
    float* out = (float*)d_out;

    float *g_PQ_p, *g_agg_p, *g_G_p, *g_hp_p, *g_s1_p, *g_s2_p, *g_B1_p, *g_Wcat_p, *g_bias1_p;
    cudaGetSymbolAddress((void**)&g_PQ_p, g_PQ);
    cudaGetSymbolAddress((void**)&g_agg_p, g_agg);
    cudaGetSymbolAddress((void**)&g_G_p, g_G);
    cudaGetSymbolAddress((void**)&g_hp_p, g_hp);
    cudaGetSymbolAddress((void**)&g_s1_p, g_s1);
    cudaGetSymbolAddress((void**)&g_s2_p, g_s2);
    cudaGetSymbolAddress((void**)&g_B1_p, g_B1);
    cudaGetSymbolAddress((void**)&g_Wcat_p, g_Wcat);
    cudaGetSymbolAddress((void**)&g_bias1_p, g_bias1);

    detect_kernel<<<1, 1>>>(edst);
    prep_kernel<<<768, 256>>>(W_pre, b_pre, W_post);
    hist_kernel<<<(NE + 255) / 256, 256>>>(edst);
    scan_kernel<<<1, 1024>>>();
    scatter_kernel<<<(NE + 255) / 256, 256>>>(esrc, edst);

    // GEMM1: PQ = h @ B1 (+ bias1)   M=50000, N=256, K=128
    {
        dim3 grid((NN + 127) / 128, 2);
        sgemm_kernel<<<grid, 256>>>(h, g_B1_p, g_PQ_p, NN, 256, 128, 0,
                                    g_bias1_p, nullptr, nullptr, nullptr, nullptr);
    }

    aggregate_kernel<<<NN, 128>>>();

    // GEMM2: G = agg @ Wcat   M=50000, N=384, K=512
    {
        dim3 grid((NN + 127) / 128, 3);
        sgemm_kernel<<<grid, 256>>>(g_agg_p, g_Wcat_p, g_G_p, NN, 384, 512, 0,
                                    nullptr, nullptr, nullptr, nullptr, nullptr);
    }

    // GEMM3: hp = relu(h @ W_post[0:128] + comb(G, s1, s2) + b_post)
    {
        dim3 grid((NN + 127) / 128, 1);
        sgemm_kernel<<<grid, 256>>>(h, W_post, g_hp_p, NN, 128, 128, 1,
                                    b_post, g_G_p, g_s1_p, g_s2_p, nullptr);
    }

    // GEMM4: out = h + leaky_relu(hp @ W_mix + b_mix)
    {
        dim3 grid((NN + 127) / 128, 1);
        sgemm_kernel<<<grid, 256>>>(g_hp_p, W_mix, out, NN, 128, 128, 2,
                                    b_mix, nullptr, nullptr, nullptr, h);
    }
}